// round 1
// baseline (speedup 1.0000x reference)
#include <cuda_runtime.h>

// out[row, :] = x[row, :] - sum(x[row, :])
// x: [R, 512] fp32, R = 8*8192 = 65536
// One warp per row: 16 floats/lane as 4x float4, warp-shuffle reduce, subtract, store.

static constexpr int D = 512;
static constexpr int WARPS_PER_BLOCK = 8;

__global__ void __launch_bounds__(WARPS_PER_BLOCK * 32)
neg_sum_add_kernel(const float* __restrict__ x, float* __restrict__ out, int nrows) {
    int warp = threadIdx.x >> 5;
    int lane = threadIdx.x & 31;
    int row = blockIdx.x * WARPS_PER_BLOCK + warp;
    if (row >= nrows) return;

    const float4* __restrict__ xr = reinterpret_cast<const float4*>(x + (size_t)row * D);
    float4* __restrict__ orow = reinterpret_cast<float4*>(out + (size_t)row * D);

    // 512 floats = 128 float4 per row; 32 lanes * 4 float4 each.
    float4 v0 = xr[lane];
    float4 v1 = xr[lane + 32];
    float4 v2 = xr[lane + 64];
    float4 v3 = xr[lane + 96];

    float s = (v0.x + v0.y) + (v0.z + v0.w)
            + (v1.x + v1.y) + (v1.z + v1.w)
            + (v2.x + v2.y) + (v2.z + v2.w)
            + (v3.x + v3.y) + (v3.z + v3.w);

    #pragma unroll
    for (int off = 16; off > 0; off >>= 1)
        s += __shfl_xor_sync(0xffffffffu, s, off);

    v0.x -= s; v0.y -= s; v0.z -= s; v0.w -= s;
    v1.x -= s; v1.y -= s; v1.z -= s; v1.w -= s;
    v2.x -= s; v2.y -= s; v2.z -= s; v2.w -= s;
    v3.x -= s; v3.y -= s; v3.z -= s; v3.w -= s;

    orow[lane]      = v0;
    orow[lane + 32] = v1;
    orow[lane + 64] = v2;
    orow[lane + 96] = v3;
}

extern "C" void kernel_launch(void* const* d_in, const int* in_sizes, int n_in,
                              void* d_out, int out_size) {
    const float* x = (const float*)d_in[0];
    float* out = (float*)d_out;
    int nrows = in_sizes[0] / D;
    int blocks = (nrows + WARPS_PER_BLOCK - 1) / WARPS_PER_BLOCK;
    neg_sum_add_kernel<<<blocks, WARPS_PER_BLOCK * 32>>>(x, out, nrows);
}